// round 2
// baseline (speedup 1.0000x reference)
#include <cuda_runtime.h>

// Stickbreaking attention, fp32, B=2 H=16 S=1024 D=64.
//
// w[i,k] = exp( x_ik + lb_ik + S_ik ),  lb = logsigmoid(-x) <= 0,
//          S_ik = suffix sum of lb over keys k..i  (<= 0, stable).
// Stream key blocks DESCENDING, carrying per-row accumulator A_i.
//
// BQ=64 q-rows/CTA, BK=64 keys/block, 128 threads, 8x4 register tile.

#define SEQ     1024
#define DHEAD   64
#define BQ      64
#define BK      64
#define THREADS 128
#define NQB     (SEQ / BQ)   // 16 q-tiles

// XOR swizzle on float4 chunks: row r, chunk c4 (0..15)
__device__ __forceinline__ int swz(int r, int c4) {
    return r * 16 + (c4 ^ ((r >> 2) & 15));
}

__global__ __launch_bounds__(THREADS, 3)
void stickbreaking_kernel(const float* __restrict__ q,
                          const float* __restrict__ k,
                          const float* __restrict__ v,
                          float* __restrict__ out) {
    extern __shared__ float4 smem[];
    float4* Qs = smem;            // 64x16 = 1024 float4 (16 KB)
    float4* Ks = smem + 1024;     // 16 KB
    float4* Vs = smem + 2048;     // 16 KB
    float4* Ws = smem + 3072;     // 16 KB

    const int tid = threadIdx.x;
    const int rg  = tid >> 4;     // 0..7 : rows 8*rg .. 8*rg+7
    const int kg  = tid & 15;     // 0..15: keys 4*kg .. 4*kg+3
    const int bh  = blockIdx.y;
    const int qb  = (NQB - 1) - blockIdx.x;   // heaviest tiles first
    const int qbase = qb * BQ;

    const float* qb_base = q   + (size_t)bh * SEQ * DHEAD;
    const float* kb_base = k   + (size_t)bh * SEQ * DHEAD;
    const float* vb_base = v   + (size_t)bh * SEQ * DHEAD;
    float*       ob_base = out + (size_t)bh * SEQ * DHEAD;

    // ---- load Q tile [BQ x 64], swizzled ----
    {
        const float4* g = (const float4*)(qb_base + (size_t)qbase * DHEAD);
        #pragma unroll
        for (int i = 0; i < 8; i++) {
            int f = i * THREADS + tid;   // 0..1023
            int r = f >> 4, c4 = f & 15;
            Qs[swz(r, c4)] = g[f];
        }
    }

    float acc[8][4];
    #pragma unroll
    for (int i = 0; i < 8; i++)
        #pragma unroll
        for (int j = 0; j < 4; j++) acc[i][j] = 0.f;
    float A[8];
    #pragma unroll
    for (int i = 0; i < 8; i++) A[i] = 0.f;

    const int nkb = qb + 1;  // key blocks covering keys 0 .. qbase+63

    #pragma unroll 1
    for (int kb = nkb - 1; kb >= 0; --kb) {
        const int kbase = kb * BK;
        const bool diag = (kb == qb);

        __syncthreads();  // prev PV done before overwriting K/V (also orders Q store)
        {
            const float4* gk = (const float4*)(kb_base + (size_t)kbase * DHEAD);
            const float4* gv = (const float4*)(vb_base + (size_t)kbase * DHEAD);
            #pragma unroll
            for (int i = 0; i < 8; i++) {
                int f = i * THREADS + tid;
                int r = f >> 4, c4 = f & 15;
                Ks[swz(r, c4)] = gk[f];
                Vs[swz(r, c4)] = gv[f];
            }
        }
        __syncthreads();

        // ---- QK^T : 8x4 score tile per thread ----
        float s[8][4];
        #pragma unroll
        for (int i = 0; i < 8; i++)
            #pragma unroll
            for (int j = 0; j < 4; j++) s[i][j] = 0.f;

        #pragma unroll
        for (int d4 = 0; d4 < 16; ++d4) {
            float4 qv[8], kv[4];
            #pragma unroll
            for (int i = 0; i < 8; i++)
                qv[i] = Qs[(8 * rg + i) * 16 + (d4 ^ ((2 * rg + (i >> 2)) & 15))];
            #pragma unroll
            for (int j = 0; j < 4; j++)
                kv[j] = Ks[(4 * kg + j) * 16 + (d4 ^ kg)];
            #pragma unroll
            for (int i = 0; i < 8; i++)
                #pragma unroll
                for (int j = 0; j < 4; j++) {
                    s[i][j] = fmaf(qv[i].x, kv[j].x, s[i][j]);
                    s[i][j] = fmaf(qv[i].y, kv[j].y, s[i][j]);
                    s[i][j] = fmaf(qv[i].z, kv[j].z, s[i][j]);
                    s[i][j] = fmaf(qv[i].w, kv[j].w, s[i][j]);
                }
        }

        // ---- elementwise + per-row suffix scan (16 lanes per row group) ----
        const unsigned li = (unsigned)kg;
        #pragma unroll
        for (int i = 0; i < 8; i++) {
            const int row_g = qbase + 8 * rg + i;
            float lb[4], c[4];
            #pragma unroll
            for (int j = 0; j < 4; j++) {
                float xx = s[i][j] * 0.125f;  // 1/sqrt(64)
                float l  = -(fmaxf(xx, 0.f) + __logf(1.f + __expf(-fabsf(xx))));
                if (diag) {
                    bool valid = (kbase + 4 * kg + j) <= row_g;
                    lb[j] = valid ? l : 0.f;
                    c[j]  = valid ? (xx + l) : -1e30f;
                } else {
                    lb[j] = l;
                    c[j]  = xx + l;
                }
            }
            float tloc = lb[0] + lb[1] + lb[2] + lb[3];
            float incl = tloc;  // inclusive suffix sum over 16 lanes
            #pragma unroll
            for (int dlt = 1; dlt < 16; dlt <<= 1) {
                float o = __shfl_down_sync(0xffffffffu, incl, dlt, 16);
                if (li + dlt < 16) incl += o;
            }
            float total = __shfl_sync(0xffffffffu, incl, 0, 16);
            float run = A[i] + (incl - tloc);  // lb over keys with higher kg
            float wv0, wv1, wv2, wv3;
            run += lb[3]; wv3 = __expf(c[3] + run);
            run += lb[2]; wv2 = __expf(c[2] + run);
            run += lb[1]; wv1 = __expf(c[1] + run);
            run += lb[0]; wv0 = __expf(c[0] + run);
            A[i] += total;
            Ws[(8 * rg + i) * 16 + (kg ^ ((2 * rg + (i >> 2)) & 15))] =
                make_float4(wv0, wv1, wv2, wv3);
        }
        __syncwarp();  // producers/consumers of a row group share a 16-lane group

        // ---- PV : acc[8 rows][4 dims] += W[8 rows][:] * V[:][4 dims] ----
        #pragma unroll
        for (int j4 = 0; j4 < 16; ++j4) {
            float4 w4[8];
            #pragma unroll
            for (int i = 0; i < 8; i++)
                w4[i] = Ws[(8 * rg + i) * 16 + (j4 ^ ((2 * rg + (i >> 2)) & 15))];
            #pragma unroll
            for (int m = 0; m < 4; m++) {
                float4 vm = Vs[(4 * j4 + m) * 16 + (kg ^ j4)];
                #pragma unroll
                for (int i = 0; i < 8; i++) {
                    float wm = (m == 0) ? w4[i].x : (m == 1) ? w4[i].y
                             : (m == 2) ? w4[i].z : w4[i].w;
                    acc[i][0] = fmaf(wm, vm.x, acc[i][0]);
                    acc[i][1] = fmaf(wm, vm.y, acc[i][1]);
                    acc[i][2] = fmaf(wm, vm.z, acc[i][2]);
                    acc[i][3] = fmaf(wm, vm.w, acc[i][3]);
                }
            }
        }
        __syncwarp();  // Ws reads done before next iteration's writes
    }

    // ---- write output tile (coalesced float4) ----
    #pragma unroll
    for (int i = 0; i < 8; i++) {
        float4 o = make_float4(acc[i][0], acc[i][1], acc[i][2], acc[i][3]);
        ((float4*)(ob_base + (size_t)(qbase + 8 * rg + i) * DHEAD))[kg] = o;
    }
}

extern "C" void kernel_launch(void* const* d_in, const int* in_sizes, int n_in,
                              void* d_out, int out_size) {
    const float* q = (const float*)d_in[0];
    const float* k = (const float*)d_in[1];
    const float* v = (const float*)d_in[2];
    float* out = (float*)d_out;
    (void)in_sizes; (void)n_in; (void)out_size;

    const int smem_bytes = 4096 * 16;  // 64 KB dynamic
    cudaFuncSetAttribute(stickbreaking_kernel,
                         cudaFuncAttributeMaxDynamicSharedMemorySize, smem_bytes);

    dim3 grid(NQB, 32);   // 16 q-tiles (heaviest first) x (B*H = 32)
    dim3 block(THREADS);
    stickbreaking_kernel<<<grid, block, smem_bytes>>>(q, k, v, out);
}